// round 6
// baseline (speedup 1.0000x reference)
#include <cuda_runtime.h>
#include <math.h>

// Problem constants
#define Bn   32
#define Nn   256
#define Hn   64
#define EPSf 1e-6f

// Table: KI intervals over [0, DMAX], interleaved (cf, cfp) float4 pairs
#define KI    512
#define DMAXf 20.0f

// Persistent-kernel shape: all blocks co-resident (128 <= 148 SMs)
#define NB 128
#define NT 1024

// Device scratch
__device__ float4   g_tab[2 * KI];     // [2k]=cf coeffs, [2k+1]=cfp coeffs
__device__ float    g_bsum[Bn * 4];    // per-batch: sum v0,v1,v2, sum tr
__device__ unsigned g_bar_cnt[2];
__device__ unsigned g_bar_gen[2];

// Replay-safe grid barrier (generation counter; all NB blocks co-resident).
__device__ __forceinline__ void grid_barrier(int id)
{
    __syncthreads();
    if (threadIdx.x == 0) {
        __threadfence();
        unsigned gen = atomicAdd(&g_bar_gen[id], 0u);
        unsigned tkt = atomicAdd(&g_bar_cnt[id], 1u);
        if (tkt == NB - 1) {
            atomicExch(&g_bar_cnt[id], 0u);
            __threadfence();
            atomicAdd(&g_bar_gen[id], 1u);
        } else {
            while (atomicAdd(&g_bar_gen[id], 0u) == gen) { }
        }
        __threadfence();
    }
    __syncthreads();
}

__device__ __forceinline__ float fast_tanh(float z)
{
    float az = fabsf(z);
    float e  = __expf(-2.f * az);
    float t  = __fdividef(1.f - e, 1.f + e);
    return copysignf(t, z);
}

// ---------------------------------------------------------------------------
__global__ void __launch_bounds__(NT, 1)
fused_kernel(const float* __restrict__ t_in,
             const float* __restrict__ x,
             const float* __restrict__ W1,   // (2,64)
             const float* __restrict__ b1,   // (64)
             const float* __restrict__ W2,   // (64,64)
             const float* __restrict__ b2,   // (64)
             const float* __restrict__ W3,   // (64,1)
             const float* __restrict__ b3,   // (1)
             float*       __restrict__ out)
{
    const int tid = threadIdx.x;
    const int blk = blockIdx.x;

    __shared__ float  sW2[Hn * Hn];      // 16 KB (phase A only)
    __shared__ float4 stab[2 * KI];      // 16 KB (phase B): interleaved table
    __shared__ float4 sh1[5][Hn];
    __shared__ float4 s_node[6];
    __shared__ float  s_red[5][2][3];
    __shared__ float  sxs[Nn * 3];       // batch positions
    __shared__ float  s_wpart[32][4];    // per-warp batch-sum partials

    const float hstep    = DMAXf / (float)KI;
    const float inv_step = (float)KI / DMAXf;

    // Phase-B identity (needed early for xs prefetch)
    const int b     = blk >> 2;
    const int ibase = (blk & 3) * 64;

    // =========================== Phase A: table ===========================
    {
        // prefetch xs (independent of table) + zero batch accumulators
        for (int idx = tid; idx < Nn * 3; idx += NT)
            sxs[idx] = x[b * Nn * 3 + idx];
        if (blk == 0 && tid < Bn * 4)
            g_bsum[tid] = 0.f;

        // stage W2 (1024 threads x 1 float4)
        reinterpret_cast<float4*>(sW2)[tid] =
            reinterpret_cast<const float4*>(W2)[tid];

        const int slot = tid >> 6;        // 0..15; slots 0..4 active
        const int p    = tid & 63;
        const int node = blk * 4 + slot;  // block owns nodes 4b..4b+4
        const float t  = t_in[0];
        const float d  = (float)node * hstep;

        if (slot < 5) {
            float w0 = W1[p];
            float z  = fmaf(d, w0, fmaf(t, W1[64 + p], b1[p]));
            float h1 = fast_tanh(z);
            float e1 = 1.f - h1 * h1;
            float gg  = e1 * w0;
            float ggd = -2.f * h1 * gg * w0;
            sh1[slot][p] = make_float4(h1, gg, ggd, 0.f);
        }
        __syncthreads();

        float pf = 0.f, pfp = 0.f, pfpp = 0.f;
        if (slot < 5) {
            float s  = b2[p];
            float sd = 0.f, sdd = 0.f;
#pragma unroll 8
            for (int l = 0; l < Hn; l++) {
                float  w2 = sW2[l * 64 + p];
                float4 hv = sh1[slot][l];
                s   = fmaf(w2, hv.x, s);
                sd  = fmaf(w2, hv.y, sd);
                sdd = fmaf(w2, hv.z, sdd);
            }
            float h2 = fast_tanh(s);
            float e2 = 1.f - h2 * h2;
            float w3 = W3[p];
            pf   = w3 * h2;
            pfp  = w3 * e2 * sd;
            pfpp = w3 * fmaf(-2.f * h2 * e2 * sd, sd, e2 * sdd);
        }

        const unsigned FULL = 0xffffffffu;
#pragma unroll
        for (int off = 16; off; off >>= 1) {
            pf   += __shfl_down_sync(FULL, pf,   off);
            pfp  += __shfl_down_sync(FULL, pfp,  off);
            pfpp += __shfl_down_sync(FULL, pfpp, off);
        }
        if (slot < 5 && (p & 31) == 0) {
            int ws = p >> 5;
            s_red[slot][ws][0] = pf;
            s_red[slot][ws][1] = pfp;
            s_red[slot][ws][2] = pfpp;
        }
        __syncthreads();
        if (slot < 5 && p == 0) {
            s_node[slot] = make_float4(
                s_red[slot][0][0] + s_red[slot][1][0] + b3[0],
                s_red[slot][0][1] + s_red[slot][1][1],
                s_red[slot][0][2] + s_red[slot][1][2], 0.f);
        }
        __syncthreads();

        // Hermite -> power basis; threads 0..3 own one interval each
        if (tid < 4) {
            float4 n0 = s_node[tid];
            float4 n1 = s_node[tid + 1];
            int idx = blk * 4 + tid;
            float P0 = n0.x, P1 = n1.x, M0 = hstep * n0.y, M1 = hstep * n1.y;
            g_tab[2 * idx] = make_float4(P0, M0,
                                         3.f * (P1 - P0) - 2.f * M0 - M1,
                                         2.f * (P0 - P1) + M0 + M1);
            float Q0 = n0.y, Q1 = n1.y, R0 = hstep * n0.z, R1 = hstep * n1.z;
            g_tab[2 * idx + 1] = make_float4(Q0, R0,
                                             3.f * (Q1 - Q0) - 2.f * R0 - R1,
                                             2.f * (Q0 - Q1) + R0 + R1);
        }
    }

    grid_barrier(0);

    // ===== copy full table into smem (one coalesced float4 per thread) =====
    stab[tid] = g_tab[tid];              // 1024 float4 = 16 KB
    __syncthreads();

    // =========================== Phase B: pairs ===========================
    const int w    = tid >> 5;
    const int lane = tid & 31;
    const int iA   = ibase + w;
    const int iB   = iA + 32;

    float vA0, vA1, vA2, tA;             // survive barrier 1 in registers
    float vB0, vB1, vB2, tB;
    {
        const float a0 = sxs[3 * iA + 0], a1 = sxs[3 * iA + 1], a2 = sxs[3 * iA + 2];
        const float e0 = sxs[3 * iB + 0], e1 = sxs[3 * iB + 1], e2 = sxs[3 * iB + 2];

        float cA0 = 0.f, cA1 = 0.f, cA2 = 0.f, sTA = 0.f;
        float cB0 = 0.f, cB1 = 0.f, cB2 = 0.f, sTB = 0.f;

#pragma unroll
        for (int jj = 0; jj < 8; jj++) {
            int j = jj * 32 + lane;
            float xj0 = sxs[3 * j + 0];
            float xj1 = sxs[3 * j + 1];
            float xj2 = sxs[3 * j + 2];

            // pair (iA, j)
            {
                float r0 = a0 - xj0, r1 = a1 - xj1, r2 = a2 - xj2;
                float d2   = fmaf(r0, r0, fmaf(r1, r1, fmaf(r2, r2, EPSf)));
                float rinv = rsqrtf(d2);
                float u = fminf(d2 * rinv * inv_step, (float)KI - 0.001f);
                int   k = (int)u;
                float wf = u - (float)k;
                float4 A  = stab[2 * k];
                float4 Bc = stab[2 * k + 1];
                float f  = fmaf(fmaf(fmaf(A.w,  wf, A.z),  wf, A.y),  wf, A.x);
                float fp = fmaf(fmaf(fmaf(Bc.w, wf, Bc.z), wf, Bc.y), wf, Bc.x);
                float mask = (j == iA) ? 0.f : 1.f;
                float fm = f * mask;
                cA0 = fmaf(r0, fm, cA0);
                cA1 = fmaf(r1, fm, cA1);
                cA2 = fmaf(r2, fm, cA2);
                sTA = fmaf(fmaf(fp * (d2 - EPSf), rinv, 3.f * f), mask, sTA);
            }
            // pair (iB, j)
            {
                float r0 = e0 - xj0, r1 = e1 - xj1, r2 = e2 - xj2;
                float d2   = fmaf(r0, r0, fmaf(r1, r1, fmaf(r2, r2, EPSf)));
                float rinv = rsqrtf(d2);
                float u = fminf(d2 * rinv * inv_step, (float)KI - 0.001f);
                int   k = (int)u;
                float wf = u - (float)k;
                float4 A  = stab[2 * k];
                float4 Bc = stab[2 * k + 1];
                float f  = fmaf(fmaf(fmaf(A.w,  wf, A.z),  wf, A.y),  wf, A.x);
                float fp = fmaf(fmaf(fmaf(Bc.w, wf, Bc.z), wf, Bc.y), wf, Bc.x);
                float mask = (j == iB) ? 0.f : 1.f;
                float fm = f * mask;
                cB0 = fmaf(r0, fm, cB0);
                cB1 = fmaf(r1, fm, cB1);
                cB2 = fmaf(r2, fm, cB2);
                sTB = fmaf(fmaf(fp * (d2 - EPSf), rinv, 3.f * f), mask, sTB);
            }
        }

        const unsigned FULL = 0xffffffffu;
#pragma unroll
        for (int off = 16; off; off >>= 1) {
            cA0 += __shfl_down_sync(FULL, cA0, off);
            cA1 += __shfl_down_sync(FULL, cA1, off);
            cA2 += __shfl_down_sync(FULL, cA2, off);
            sTA += __shfl_down_sync(FULL, sTA, off);
            cB0 += __shfl_down_sync(FULL, cB0, off);
            cB1 += __shfl_down_sync(FULL, cB1, off);
            cB2 += __shfl_down_sync(FULL, cB2, off);
            sTB += __shfl_down_sync(FULL, sTB, off);
        }

        const float invNm1 = 1.f / (float)(Nn - 1);
        vA0 = cA0 * invNm1; vA1 = cA1 * invNm1; vA2 = cA2 * invNm1; tA = sTA * invNm1;
        vB0 = cB0 * invNm1; vB1 = cB1 * invNm1; vB2 = cB2 * invNm1; tB = sTB * invNm1;

        // block-local batch-sum reduction, then 4 atomics
        if (lane == 0) {
            s_wpart[w][0] = vA0 + vB0;
            s_wpart[w][1] = vA1 + vB1;
            s_wpart[w][2] = vA2 + vB2;
            s_wpart[w][3] = tA  + tB;
        }
        __syncthreads();
        if (tid < 4) {
            float acc = 0.f;
#pragma unroll
            for (int ww = 0; ww < 32; ww++) acc += s_wpart[ww][tid];
            atomicAdd(&g_bsum[b * 4 + tid], acc);
        }
    }

    grid_barrier(1);

    // ========================= Phase C: finalize ==========================
    if (lane == 0) {
        const float invN = 1.f / (float)Nn;
        float m0 = g_bsum[b * 4 + 0] * invN;
        float m1 = g_bsum[b * 4 + 1] * invN;
        float m2 = g_bsum[b * 4 + 2] * invN;
        float* yb = out + b * (Nn * 3);
        yb[iA * 3 + 0] = vA0 - m0;
        yb[iA * 3 + 1] = vA1 - m1;
        yb[iA * 3 + 2] = vA2 - m2;
        yb[iB * 3 + 0] = vB0 - m0;
        yb[iB * 3 + 1] = vB1 - m1;
        yb[iB * 3 + 2] = vB2 - m2;
    }
    if ((blk & 3) == 0 && tid == 0)
        out[Bn * Nn * 3 + b] = g_bsum[b * 4 + 3] * (1.f - 1.f / (float)Nn);
}

// ---------------------------------------------------------------------------
extern "C" void kernel_launch(void* const* d_in, const int* in_sizes, int n_in,
                              void* d_out, int out_size)
{
    const float* t  = (const float*)d_in[0];
    const float* x  = (const float*)d_in[1];
    const float* W1 = (const float*)d_in[2];
    const float* b1 = (const float*)d_in[3];
    const float* W2 = (const float*)d_in[4];
    const float* b2 = (const float*)d_in[5];
    const float* W3 = (const float*)d_in[6];
    const float* b3 = (const float*)d_in[7];

    fused_kernel<<<NB, NT>>>(t, x, W1, b1, W2, b2, W3, b3, (float*)d_out);
}

// round 7
// speedup vs baseline: 1.3099x; 1.3099x over previous
#include <cuda_runtime.h>
#include <math.h>

// Problem constants
#define Bn   32
#define Nn   256
#define Hn   64
#define EPSf 1e-6f

// Table: KI intervals over [0, DMAX]; ONE float4 (f-cubic, power basis) each.
// f' is evaluated as the analytic derivative of the same cubic.
#define KI    512
#define DMAXf 20.0f

// Persistent-kernel shape: all blocks co-resident (128 <= 148 SMs)
#define NB 128
#define NT 1024

// Device scratch
__device__ float4   g_tab[KI];
__device__ float    g_bsum[Bn * 4];    // per-batch: sum v0,v1,v2, sum tr
__device__ unsigned g_bar_cnt[2];
__device__ unsigned g_bar_gen[2];

// Replay-safe grid barrier (generation counter; all NB blocks co-resident).
__device__ __forceinline__ void grid_barrier(int id)
{
    __syncthreads();
    if (threadIdx.x == 0) {
        __threadfence();
        unsigned gen = atomicAdd(&g_bar_gen[id], 0u);
        unsigned tkt = atomicAdd(&g_bar_cnt[id], 1u);
        if (tkt == NB - 1) {
            atomicExch(&g_bar_cnt[id], 0u);
            __threadfence();
            atomicAdd(&g_bar_gen[id], 1u);
        } else {
            while (atomicAdd(&g_bar_gen[id], 0u) == gen) { }
        }
        __threadfence();
    }
    __syncthreads();
}

__device__ __forceinline__ float fast_tanh(float z)
{
    float az = fabsf(z);
    float e  = __expf(-2.f * az);
    float t  = __fdividef(1.f - e, 1.f + e);
    return copysignf(t, z);
}

// ---------------------------------------------------------------------------
__global__ void __launch_bounds__(NT, 1)
fused_kernel(const float* __restrict__ t_in,
             const float* __restrict__ x,
             const float* __restrict__ W1,   // (2,64)
             const float* __restrict__ b1,   // (64)
             const float* __restrict__ W2,   // (64,64)
             const float* __restrict__ b2,   // (64)
             const float* __restrict__ W3,   // (64,1)
             const float* __restrict__ b3,   // (1)
             float*       __restrict__ out)
{
    const int tid = threadIdx.x;
    const int blk = blockIdx.x;

    __shared__ float  sW2[Hn * Hn];      // 16 KB (phase A only)
    __shared__ float4 stab[KI];          // 8 KB  (phase B table)
    __shared__ float2 sh1[5][Hn];        // layer-1 (h1, dh1/dd)
    __shared__ float2 s_node[6];         // (f, f') at 5 nodes
    __shared__ float  s_red[5][2][2];
    __shared__ float  sxs[Nn * 3];
    __shared__ float  s_wpart[32][4];

    const float hstep    = DMAXf / (float)KI;
    const float inv_step = (float)KI / DMAXf;   // == 1/hstep

    const int b     = blk >> 2;
    const int ibase = (blk & 3) * 64;

    // =========================== Phase A: table ===========================
    {
        for (int idx = tid; idx < Nn * 3; idx += NT)
            sxs[idx] = x[b * Nn * 3 + idx];
        if (blk == 0 && tid < Bn * 4)
            g_bsum[tid] = 0.f;

        reinterpret_cast<float4*>(sW2)[tid] =
            reinterpret_cast<const float4*>(W2)[tid];

        const int slot = tid >> 6;        // slots 0..4 active
        const int p    = tid & 63;
        const int node = blk * 4 + slot;
        const float t  = t_in[0];
        const float d  = (float)node * hstep;

        if (slot < 5) {
            float w0 = W1[p];
            float z  = fmaf(d, w0, fmaf(t, W1[64 + p], b1[p]));
            float h1 = fast_tanh(z);
            float e1 = 1.f - h1 * h1;
            sh1[slot][p] = make_float2(h1, e1 * w0);
        }
        __syncthreads();

        float pf = 0.f, pfp = 0.f;
        if (slot < 5) {
            float s  = b2[p];
            float sd = 0.f;
#pragma unroll 8
            for (int l = 0; l < Hn; l++) {
                float  w2 = sW2[l * 64 + p];
                float2 hv = sh1[slot][l];
                s  = fmaf(w2, hv.x, s);
                sd = fmaf(w2, hv.y, sd);
            }
            float h2 = fast_tanh(s);
            float e2 = 1.f - h2 * h2;
            float w3 = W3[p];
            pf  = w3 * h2;
            pfp = w3 * e2 * sd;
        }

        const unsigned FULL = 0xffffffffu;
#pragma unroll
        for (int off = 16; off; off >>= 1) {
            pf  += __shfl_down_sync(FULL, pf,  off);
            pfp += __shfl_down_sync(FULL, pfp, off);
        }
        if (slot < 5 && (p & 31) == 0) {
            int ws = p >> 5;
            s_red[slot][ws][0] = pf;
            s_red[slot][ws][1] = pfp;
        }
        __syncthreads();
        if (slot < 5 && p == 0) {
            s_node[slot] = make_float2(
                s_red[slot][0][0] + s_red[slot][1][0] + b3[0],
                s_red[slot][0][1] + s_red[slot][1][1]);
        }
        __syncthreads();

        // Hermite -> power basis (f only); threads 0..3 own one interval.
        if (tid < 4) {
            float2 n0 = s_node[tid];
            float2 n1 = s_node[tid + 1];
            float P0 = n0.x, P1 = n1.x;
            float M0 = hstep * n0.y, M1 = hstep * n1.y;
            g_tab[blk * 4 + tid] = make_float4(
                P0, M0,
                3.f * (P1 - P0) - 2.f * M0 - M1,
                2.f * (P0 - P1) + M0 + M1);
        }
    }

    grid_barrier(0);

    // copy table to smem (512 float4, coalesced)
    if (tid < KI) stab[tid] = g_tab[tid];
    __syncthreads();

    // =========================== Phase B: pairs ===========================
    const int w    = tid >> 5;
    const int lane = tid & 31;
    const int iA   = ibase + w;
    const int iB   = iA + 32;

    float vA0, vA1, vA2, tA;
    float vB0, vB1, vB2, tB;
    {
        const float a0 = sxs[3 * iA + 0], a1 = sxs[3 * iA + 1], a2 = sxs[3 * iA + 2];
        const float e0 = sxs[3 * iB + 0], e1 = sxs[3 * iB + 1], e2 = sxs[3 * iB + 2];

        float cA0 = 0.f, cA1 = 0.f, cA2 = 0.f, sTA = 0.f;
        float cB0 = 0.f, cB1 = 0.f, cB2 = 0.f, sTB = 0.f;

#pragma unroll
        for (int jj = 0; jj < 8; jj++) {
            int j = jj * 32 + lane;
            float xj0 = sxs[3 * j + 0];
            float xj1 = sxs[3 * j + 1];
            float xj2 = sxs[3 * j + 2];

            // pair (iA, j)
            {
                float r0 = a0 - xj0, r1 = a1 - xj1, r2 = a2 - xj2;
                float d2   = fmaf(r0, r0, fmaf(r1, r1, fmaf(r2, r2, EPSf)));
                float rinv = rsqrtf(d2);
                float u = fminf(d2 * rinv * inv_step, (float)KI - 0.001f);
                int   k = (int)u;
                float wf = u - (float)k;
                float4 A = stab[k];
                float f   = fmaf(fmaf(fmaf(A.w, wf, A.z), wf, A.y), wf, A.x);
                float fpw = fmaf(fmaf(3.f * A.w, wf, 2.f * A.z), wf, A.y);
                float fp  = fpw * inv_step;              // df/dd
                float mask = (j == iA) ? 0.f : 1.f;
                float fm = f * mask;
                cA0 = fmaf(r0, fm, cA0);
                cA1 = fmaf(r1, fm, cA1);
                cA2 = fmaf(r2, fm, cA2);
                sTA = fmaf(fmaf(fp * (d2 - EPSf), rinv, 3.f * f), mask, sTA);
            }
            // pair (iB, j)
            {
                float r0 = e0 - xj0, r1 = e1 - xj1, r2 = e2 - xj2;
                float d2   = fmaf(r0, r0, fmaf(r1, r1, fmaf(r2, r2, EPSf)));
                float rinv = rsqrtf(d2);
                float u = fminf(d2 * rinv * inv_step, (float)KI - 0.001f);
                int   k = (int)u;
                float wf = u - (float)k;
                float4 A = stab[k];
                float f   = fmaf(fmaf(fmaf(A.w, wf, A.z), wf, A.y), wf, A.x);
                float fpw = fmaf(fmaf(3.f * A.w, wf, 2.f * A.z), wf, A.y);
                float fp  = fpw * inv_step;
                float mask = (j == iB) ? 0.f : 1.f;
                float fm = f * mask;
                cB0 = fmaf(r0, fm, cB0);
                cB1 = fmaf(r1, fm, cB1);
                cB2 = fmaf(r2, fm, cB2);
                sTB = fmaf(fmaf(fp * (d2 - EPSf), rinv, 3.f * f), mask, sTB);
            }
        }

        const unsigned FULL = 0xffffffffu;
#pragma unroll
        for (int off = 16; off; off >>= 1) {
            cA0 += __shfl_down_sync(FULL, cA0, off);
            cA1 += __shfl_down_sync(FULL, cA1, off);
            cA2 += __shfl_down_sync(FULL, cA2, off);
            sTA += __shfl_down_sync(FULL, sTA, off);
            cB0 += __shfl_down_sync(FULL, cB0, off);
            cB1 += __shfl_down_sync(FULL, cB1, off);
            cB2 += __shfl_down_sync(FULL, cB2, off);
            sTB += __shfl_down_sync(FULL, sTB, off);
        }

        const float invNm1 = 1.f / (float)(Nn - 1);
        vA0 = cA0 * invNm1; vA1 = cA1 * invNm1; vA2 = cA2 * invNm1; tA = sTA * invNm1;
        vB0 = cB0 * invNm1; vB1 = cB1 * invNm1; vB2 = cB2 * invNm1; tB = sTB * invNm1;

        if (lane == 0) {
            s_wpart[w][0] = vA0 + vB0;
            s_wpart[w][1] = vA1 + vB1;
            s_wpart[w][2] = vA2 + vB2;
            s_wpart[w][3] = tA  + tB;
        }
        __syncthreads();
        if (tid < 4) {
            float acc = 0.f;
#pragma unroll
            for (int ww = 0; ww < 32; ww++) acc += s_wpart[ww][tid];
            atomicAdd(&g_bsum[b * 4 + tid], acc);
        }
    }

    grid_barrier(1);

    // ========================= Phase C: finalize ==========================
    if (lane == 0) {
        const float invN = 1.f / (float)Nn;
        float m0 = g_bsum[b * 4 + 0] * invN;
        float m1 = g_bsum[b * 4 + 1] * invN;
        float m2 = g_bsum[b * 4 + 2] * invN;
        float* yb = out + b * (Nn * 3);
        yb[iA * 3 + 0] = vA0 - m0;
        yb[iA * 3 + 1] = vA1 - m1;
        yb[iA * 3 + 2] = vA2 - m2;
        yb[iB * 3 + 0] = vB0 - m0;
        yb[iB * 3 + 1] = vB1 - m1;
        yb[iB * 3 + 2] = vB2 - m2;
    }
    if ((blk & 3) == 0 && tid == 0)
        out[Bn * Nn * 3 + b] = g_bsum[b * 4 + 3] * (1.f - 1.f / (float)Nn);
}

// ---------------------------------------------------------------------------
extern "C" void kernel_launch(void* const* d_in, const int* in_sizes, int n_in,
                              void* d_out, int out_size)
{
    const float* t  = (const float*)d_in[0];
    const float* x  = (const float*)d_in[1];
    const float* W1 = (const float*)d_in[2];
    const float* b1 = (const float*)d_in[3];
    const float* W2 = (const float*)d_in[4];
    const float* b2 = (const float*)d_in[5];
    const float* W3 = (const float*)d_in[6];
    const float* b3 = (const float*)d_in[7];

    fused_kernel<<<NB, NT>>>(t, x, W1, b1, W2, b2, W3, b3, (float*)d_out);
}

// round 8
// speedup vs baseline: 1.3884x; 1.0599x over previous
#include <cuda_runtime.h>
#include <math.h>

// Problem constants
#define Bn   32
#define Nn   256
#define Hn   64
#define EPSf 1e-6f

// Table: KI intervals over [0, DMAX]; ONE float4 (f-cubic, power basis) each.
#define KI    512
#define DMAXf 20.0f

// Persistent-kernel shape: all blocks co-resident (128 <= 148 SMs)
#define NB 128
#define NT 1024

// Device scratch (zero-initialized; every launch restores zeros -> replay-safe)
__device__ float4   g_tab[KI];
__device__ float    g_v[Bn * Nn * 3];   // per-(b,i) field values
__device__ float    g_bsum[Bn * 4];     // per-batch: sum v0,v1,v2, sum tr
__device__ unsigned g_ticket[Bn];       // per-batch arrival tickets
__device__ unsigned g_bar_cnt;          // barrier 0 state
__device__ unsigned g_bar_gen;

// Grid barrier with LOAD-based polling (no atomic-RMW contention).
// Replay-safe: cnt reset by last arriver; gen monotone across replays.
__device__ __forceinline__ void grid_barrier0()
{
    __syncthreads();
    if (threadIdx.x == 0) {
        __threadfence();                              // publish phase-A writes
        volatile unsigned* genp = &g_bar_gen;
        unsigned gen = *genp;                          // snapshot before arrival
        unsigned tkt = atomicAdd(&g_bar_cnt, 1u);
        if (tkt == NB - 1) {
            atomicExch(&g_bar_cnt, 0u);
            __threadfence();
            atomicAdd(&g_bar_gen, 1u);                 // release
        } else {
            while (*genp == gen) { __nanosleep(64); }
        }
        __threadfence();                               // acquire
    }
    __syncthreads();
}

__device__ __forceinline__ float fast_tanh(float z)
{
    float az = fabsf(z);
    float e  = __expf(-2.f * az);
    float t  = __fdividef(1.f - e, 1.f + e);
    return copysignf(t, z);
}

// ---------------------------------------------------------------------------
__global__ void __launch_bounds__(NT, 1)
fused_kernel(const float* __restrict__ t_in,
             const float* __restrict__ x,
             const float* __restrict__ W1,   // (2,64)
             const float* __restrict__ b1,   // (64)
             const float* __restrict__ W2,   // (64,64)
             const float* __restrict__ b2,   // (64)
             const float* __restrict__ W3,   // (64,1)
             const float* __restrict__ b3,   // (1)
             float*       __restrict__ out)
{
    const int tid = threadIdx.x;
    const int blk = blockIdx.x;

    __shared__ float    sW2[Hn * Hn];    // 16 KB (phase A only)
    __shared__ float4   stab[KI];        // 8 KB  (phase B table)
    __shared__ float2   sh1[5][Hn];
    __shared__ float2   s_node[6];
    __shared__ float    s_red[5][2][2];
    __shared__ float    sxs[Nn * 3];
    __shared__ float    s_wpart[32][4];
    __shared__ unsigned s_tk;
    __shared__ float    s_m[4];

    const float hstep    = DMAXf / (float)KI;
    const float inv_step = (float)KI / DMAXf;

    const int b     = blk >> 2;
    const int ibase = (blk & 3) * 64;

    // =========================== Phase A: table ===========================
    {
        for (int idx = tid; idx < Nn * 3; idx += NT)
            sxs[idx] = x[b * Nn * 3 + idx];

        reinterpret_cast<float4*>(sW2)[tid] =
            reinterpret_cast<const float4*>(W2)[tid];

        const int slot = tid >> 6;        // slots 0..4 active
        const int p    = tid & 63;
        const int node = blk * 4 + slot;
        const float t  = t_in[0];
        const float d  = (float)node * hstep;

        if (slot < 5) {
            float w0 = W1[p];
            float z  = fmaf(d, w0, fmaf(t, W1[64 + p], b1[p]));
            float h1 = fast_tanh(z);
            float e1 = 1.f - h1 * h1;
            sh1[slot][p] = make_float2(h1, e1 * w0);
        }
        __syncthreads();

        float pf = 0.f, pfp = 0.f;
        if (slot < 5) {
            float s  = b2[p];
            float sd = 0.f;
#pragma unroll 8
            for (int l = 0; l < Hn; l++) {
                float  w2 = sW2[l * 64 + p];
                float2 hv = sh1[slot][l];
                s  = fmaf(w2, hv.x, s);
                sd = fmaf(w2, hv.y, sd);
            }
            float h2 = fast_tanh(s);
            float e2 = 1.f - h2 * h2;
            float w3 = W3[p];
            pf  = w3 * h2;
            pfp = w3 * e2 * sd;
        }

        const unsigned FULL = 0xffffffffu;
#pragma unroll
        for (int off = 16; off; off >>= 1) {
            pf  += __shfl_down_sync(FULL, pf,  off);
            pfp += __shfl_down_sync(FULL, pfp, off);
        }
        if (slot < 5 && (p & 31) == 0) {
            int ws = p >> 5;
            s_red[slot][ws][0] = pf;
            s_red[slot][ws][1] = pfp;
        }
        __syncthreads();
        if (slot < 5 && p == 0) {
            s_node[slot] = make_float2(
                s_red[slot][0][0] + s_red[slot][1][0] + b3[0],
                s_red[slot][0][1] + s_red[slot][1][1]);
        }
        __syncthreads();

        if (tid < 4) {
            float2 n0 = s_node[tid];
            float2 n1 = s_node[tid + 1];
            float P0 = n0.x, P1 = n1.x;
            float M0 = hstep * n0.y, M1 = hstep * n1.y;
            g_tab[blk * 4 + tid] = make_float4(
                P0, M0,
                3.f * (P1 - P0) - 2.f * M0 - M1,
                2.f * (P0 - P1) + M0 + M1);
        }
    }

    grid_barrier0();

    if (tid < KI) stab[tid] = g_tab[tid];
    __syncthreads();

    // =========================== Phase B: pairs ===========================
    const int w    = tid >> 5;
    const int lane = tid & 31;
    const int iA   = ibase + w;
    const int iB   = iA + 32;

    {
        const float a0 = sxs[3 * iA + 0], a1 = sxs[3 * iA + 1], a2 = sxs[3 * iA + 2];
        const float e0 = sxs[3 * iB + 0], e1 = sxs[3 * iB + 1], e2 = sxs[3 * iB + 2];

        float cA0 = 0.f, cA1 = 0.f, cA2 = 0.f, sTA = 0.f;
        float cB0 = 0.f, cB1 = 0.f, cB2 = 0.f, sTB = 0.f;

#pragma unroll
        for (int jj = 0; jj < 8; jj++) {
            int j = jj * 32 + lane;
            float xj0 = sxs[3 * j + 0];
            float xj1 = sxs[3 * j + 1];
            float xj2 = sxs[3 * j + 2];

            {
                float r0 = a0 - xj0, r1 = a1 - xj1, r2 = a2 - xj2;
                float d2   = fmaf(r0, r0, fmaf(r1, r1, fmaf(r2, r2, EPSf)));
                float rinv = rsqrtf(d2);
                float u = fminf(d2 * rinv * inv_step, (float)KI - 0.001f);
                int   k = (int)u;
                float wf = u - (float)k;
                float4 A = stab[k];
                float f   = fmaf(fmaf(fmaf(A.w, wf, A.z), wf, A.y), wf, A.x);
                float fpw = fmaf(fmaf(3.f * A.w, wf, 2.f * A.z), wf, A.y);
                float fp  = fpw * inv_step;
                float mask = (j == iA) ? 0.f : 1.f;
                float fm = f * mask;
                cA0 = fmaf(r0, fm, cA0);
                cA1 = fmaf(r1, fm, cA1);
                cA2 = fmaf(r2, fm, cA2);
                sTA = fmaf(fmaf(fp * (d2 - EPSf), rinv, 3.f * f), mask, sTA);
            }
            {
                float r0 = e0 - xj0, r1 = e1 - xj1, r2 = e2 - xj2;
                float d2   = fmaf(r0, r0, fmaf(r1, r1, fmaf(r2, r2, EPSf)));
                float rinv = rsqrtf(d2);
                float u = fminf(d2 * rinv * inv_step, (float)KI - 0.001f);
                int   k = (int)u;
                float wf = u - (float)k;
                float4 A = stab[k];
                float f   = fmaf(fmaf(fmaf(A.w, wf, A.z), wf, A.y), wf, A.x);
                float fpw = fmaf(fmaf(3.f * A.w, wf, 2.f * A.z), wf, A.y);
                float fp  = fpw * inv_step;
                float mask = (j == iB) ? 0.f : 1.f;
                float fm = f * mask;
                cB0 = fmaf(r0, fm, cB0);
                cB1 = fmaf(r1, fm, cB1);
                cB2 = fmaf(r2, fm, cB2);
                sTB = fmaf(fmaf(fp * (d2 - EPSf), rinv, 3.f * f), mask, sTB);
            }
        }

        const unsigned FULL = 0xffffffffu;
#pragma unroll
        for (int off = 16; off; off >>= 1) {
            cA0 += __shfl_down_sync(FULL, cA0, off);
            cA1 += __shfl_down_sync(FULL, cA1, off);
            cA2 += __shfl_down_sync(FULL, cA2, off);
            sTA += __shfl_down_sync(FULL, sTA, off);
            cB0 += __shfl_down_sync(FULL, cB0, off);
            cB1 += __shfl_down_sync(FULL, cB1, off);
            cB2 += __shfl_down_sync(FULL, cB2, off);
            sTB += __shfl_down_sync(FULL, sTB, off);
        }

        if (lane == 0) {
            const float invNm1 = 1.f / (float)(Nn - 1);
            float vA0 = cA0 * invNm1, vA1 = cA1 * invNm1, vA2 = cA2 * invNm1;
            float vB0 = cB0 * invNm1, vB1 = cB1 * invNm1, vB2 = cB2 * invNm1;
            float tAB = (sTA + sTB) * invNm1;

            int rA = b * Nn + iA;
            int rB = b * Nn + iB;
            g_v[rA * 3 + 0] = vA0;
            g_v[rA * 3 + 1] = vA1;
            g_v[rA * 3 + 2] = vA2;
            g_v[rB * 3 + 0] = vB0;
            g_v[rB * 3 + 1] = vB1;
            g_v[rB * 3 + 2] = vB2;

            s_wpart[w][0] = vA0 + vB0;
            s_wpart[w][1] = vA1 + vB1;
            s_wpart[w][2] = vA2 + vB2;
            s_wpart[w][3] = tAB;
        }
        __syncthreads();
        if (tid < 4) {
            float acc = 0.f;
#pragma unroll
            for (int ww = 0; ww < 32; ww++) acc += s_wpart[ww][tid];
            atomicAdd(&g_bsum[b * 4 + tid], acc);
        }
        __syncthreads();   // bsum atomics done before ticket
    }

    // ===== per-batch ticket: 4th arriver finalizes this batch (no grid bar) =====
    if (tid == 0) {
        __threadfence();                               // release v + bsum
        s_tk = atomicAdd(&g_ticket[b], 1u);
        if (s_tk == 3) __threadfence();                // acquire siblings' writes
    }
    __syncthreads();

    if (s_tk == 3) {
        // ========================= Phase C: finalize =========================
        if (tid < 4) s_m[tid] = g_bsum[b * 4 + tid];
        __syncthreads();

        const float invN = 1.f / (float)Nn;
        const float m0 = s_m[0] * invN;
        const float m1 = s_m[1] * invN;
        const float m2 = s_m[2] * invN;

        if (tid < Nn * 3) {
            int c = tid - (tid / 3) * 3;
            float mm = (c == 0) ? m0 : ((c == 1) ? m1 : m2);
            out[b * (Nn * 3) + tid] = g_v[b * (Nn * 3) + tid] - mm;
        }
        if (tid == 0)
            out[Bn * Nn * 3 + b] = s_m[3] * (1.f - 1.f / (float)Nn);

        __syncthreads();
        // reset per-batch state for next graph replay
        if (tid < 4) g_bsum[b * 4 + tid] = 0.f;
        if (tid == 0) g_ticket[b] = 0u;
    }
}

// ---------------------------------------------------------------------------
extern "C" void kernel_launch(void* const* d_in, const int* in_sizes, int n_in,
                              void* d_out, int out_size)
{
    const float* t  = (const float*)d_in[0];
    const float* x  = (const float*)d_in[1];
    const float* W1 = (const float*)d_in[2];
    const float* b1 = (const float*)d_in[3];
    const float* W2 = (const float*)d_in[4];
    const float* b2 = (const float*)d_in[5];
    const float* W3 = (const float*)d_in[6];
    const float* b3 = (const float*)d_in[7];

    fused_kernel<<<NB, NT>>>(t, x, W1, b1, W2, b2, W3, b3, (float*)d_out);
}